// round 4
// baseline (speedup 1.0000x reference)
#include <cuda_runtime.h>

// x is [8192, 4096] fp32 row-major. loss = N * sum(x*x) - sum_d (colsum_d)^2
#define N_ROWS   8192
#define D_COLS   4096

// Single persistent kernel: 1024 blocks x 256 threads, all resident
// (launch_bounds(256,8) -> <=32 regs -> 8 CTAs/SM capacity = 8*148 >= 1024).
#define NBLOCKS   1024
#define NTHREADS  256
#define CBLK      4                         // column groups (4 x 1024 cols)
#define RCHUNKS   (NBLOCKS / CBLK)          // 256 row chunks
#define ROWS_PER_CHUNK (N_ROWS / RCHUNKS)   // 32

// Phase 2: 128 active blocks, 32 columns each
#define P2_BLOCKS 128
#define COLS_PER_P2 (D_COLS / P2_BLOCKS)    // 32

// Scratch (__device__ globals; zero-initialized; no allocations)
__device__ float    g_colsum_part[RCHUNKS * D_COLS];   // 4 MB
__device__ float    g_ss_part[NBLOCKS];                // 1024 floats
__device__ float    g_colsq_part[P2_BLOCKS];           // 128 floats
__device__ unsigned g_bar_count = 0;
__device__ unsigned g_bar_gen   = 0;                   // monotonic across replays

// Software grid barrier. Safe because the whole grid is co-resident.
// Releaser resets count before bumping gen -> idempotent across graph replays.
__device__ __forceinline__ void grid_barrier()
{
    __syncthreads();
    if (threadIdx.x == 0) {
        volatile unsigned* genp = &g_bar_gen;
        unsigned my_gen = *genp;
        __threadfence();
        if (atomicAdd(&g_bar_count, 1u) == NBLOCKS - 1u) {
            g_bar_count = 0;
            __threadfence();
            atomicAdd(&g_bar_gen, 1u);        // release
        } else {
            while (*genp == my_gen) __nanosleep(32);
            __threadfence();
        }
    }
    __syncthreads();
}

__global__ __launch_bounds__(NTHREADS, 8)
void stability_loss_kernel(const float* __restrict__ x, float* __restrict__ out)
{
    const int t = threadIdx.x;
    const int b = blockIdx.x;

    __shared__ float sh[8][32];   // reused across phases

    // ---------------- Phase 1: stream the matrix once ----------------
    {
        const int cg    = b & (CBLK - 1);          // column group 0..3
        const int chunk = b >> 2;                  // row chunk 0..255
        const int col   = cg * (NTHREADS * 4) + t * 4;
        const int r0    = chunk * ROWS_PER_CHUNK;

        const float4* __restrict__ p =
            reinterpret_cast<const float4*>(x + (size_t)r0 * D_COLS + col);
        const int row_stride4 = D_COLS / 4;

        float4 cs = make_float4(0.f, 0.f, 0.f, 0.f);
        float  ss = 0.f;

        #pragma unroll 8
        for (int r = 0; r < ROWS_PER_CHUNK; ++r) {
            float4 v = p[(size_t)r * row_stride4];
            cs.x += v.x; cs.y += v.y; cs.z += v.z; cs.w += v.w;
            ss   += v.x * v.x + v.y * v.y + v.z * v.z + v.w * v.w;
        }

        reinterpret_cast<float4*>(g_colsum_part + (size_t)chunk * D_COLS)
            [cg * NTHREADS + t] = cs;

        // block-reduce ss
        #pragma unroll
        for (int o = 16; o > 0; o >>= 1)
            ss += __shfl_down_sync(0xffffffffu, ss, o);
        if ((t & 31) == 0) sh[0][t >> 5] = ss;
        __syncthreads();
        if (t < 8) {
            float v = sh[0][t];
            #pragma unroll
            for (int o = 4; o > 0; o >>= 1)
                v += __shfl_down_sync(0xffu, v, o);
            if (t == 0) g_ss_part[b] = v;
        }
    }

    grid_barrier();

    // ---------------- Phase 2: column sums -> squared, 128 blocks ----------------
    if (b < P2_BLOCKS) {
        const int lane = t & 31;
        const int w    = t >> 5;                  // 8 warps
        const int col  = b * COLS_PER_P2 + lane;  // coalesced 128B per warp-load

        float s = 0.f;
        #pragma unroll 4
        for (int c = w; c < RCHUNKS; c += 8)      // 32 chunks per thread
            s += g_colsum_part[(size_t)c * D_COLS + col];

        sh[w][lane] = s;
        __syncthreads();
        if (w == 0) {
            float tot = 0.f;
            #pragma unroll
            for (int i = 0; i < 8; ++i) tot += sh[i][lane];
            float sq = tot * tot;
            #pragma unroll
            for (int o = 16; o > 0; o >>= 1)
                sq += __shfl_down_sync(0xffffffffu, sq, o);
            if (lane == 0) g_colsq_part[b] = sq;
        }
    }

    grid_barrier();

    // ---------------- Phase 3: fold the tiny partials ----------------
    if (b == 0) {
        float ss = 0.f;
        #pragma unroll
        for (int i = t; i < NBLOCKS; i += NTHREADS)   // 4 each
            ss += g_ss_part[i];
        float cq = (t < P2_BLOCKS) ? g_colsq_part[t] : 0.f;

        #pragma unroll
        for (int o = 16; o > 0; o >>= 1) {
            ss += __shfl_down_sync(0xffffffffu, ss, o);
            cq += __shfl_down_sync(0xffffffffu, cq, o);
        }
        if ((t & 31) == 0) { sh[0][t >> 5] = ss; sh[1][t >> 5] = cq; }
        __syncthreads();
        if (t < 8) {
            float a = sh[0][t], c2 = sh[1][t];
            #pragma unroll
            for (int o = 4; o > 0; o >>= 1) {
                a  += __shfl_down_sync(0xffu, a,  o);
                c2 += __shfl_down_sync(0xffu, c2, o);
            }
            if (t == 0)
                out[0] = (float)N_ROWS * a - c2;
        }
    }
}

extern "C" void kernel_launch(void* const* d_in, const int* in_sizes, int n_in,
                              void* d_out, int out_size)
{
    const float* x = (const float*)d_in[0];
    float* out = (float*)d_out;
    (void)in_sizes; (void)n_in; (void)out_size;

    stability_loss_kernel<<<NBLOCKS, NTHREADS>>>(x, out);
}

// round 5
// speedup vs baseline: 1.1856x; 1.1856x over previous
#include <cuda_runtime.h>
#include <cstdint>

// x: [8192, 4096] fp32 row-major. loss = N*sum(x*x) - sum_d(colsum_d)^2
#define N_ROWS   8192
#define D_COLS   4096

#define CG        8                       // column groups (512 cols each)
#define RC        64                      // row chunks per group
#define NBLOCKS   (CG * RC)               // 512
#define NTHREADS  256
#define COLS_PER_CG     (D_COLS / CG)     // 512
#define ROWS_PER_CHUNK  (N_ROWS / RC)     // 128

#define STAGE_ROWS  4
#define NITER       (ROWS_PER_CHUNK / STAGE_ROWS)   // 32
#define NSTAGE      4
#define SEG_BYTES   (COLS_PER_CG * 4)               // 2048 contiguous bytes/row
#define STAGE_BYTES (STAGE_ROWS * SEG_BYTES)        // 8192

// Scratch (__device__ globals; no allocations allowed)
__device__ float    g_part[CG * RC * COLS_PER_CG];  // 1 MB column-sum partials
__device__ float    g_ss_part[NBLOCKS];
__device__ float    g_colsq[CG];
__device__ float    g_ss_grp[CG];
__device__ unsigned g_cnt_grp[CG];                  // reset by last arrival
__device__ unsigned g_cnt_final;                    // reset by last arrival

// ---------------- PTX helpers ----------------
__device__ __forceinline__ uint32_t smem_u32(const void* p) {
    return (uint32_t)__cvta_generic_to_shared(p);
}
__device__ __forceinline__ void mbar_init(uint32_t a, uint32_t cnt) {
    asm volatile("mbarrier.init.shared.b64 [%0], %1;" :: "r"(a), "r"(cnt) : "memory");
}
__device__ __forceinline__ void mbar_expect_tx(uint32_t a, uint32_t bytes) {
    asm volatile("mbarrier.arrive.expect_tx.shared.b64 _, [%0], %1;"
                 :: "r"(a), "r"(bytes) : "memory");
}
__device__ __forceinline__ void bulk_g2s(uint32_t dst, const void* src,
                                         uint32_t bytes, uint32_t mbar) {
    asm volatile("cp.async.bulk.shared::cta.global.mbarrier::complete_tx::bytes "
                 "[%0], [%1], %2, [%3];"
                 :: "r"(dst), "l"(src), "r"(bytes), "r"(mbar) : "memory");
}
__device__ __forceinline__ void mbar_wait(uint32_t mbar, uint32_t parity) {
    asm volatile(
        "{\n\t.reg .pred P;\n\t"
        "W_%=: mbarrier.try_wait.parity.acquire.cta.shared::cta.b64 P, [%0], %1, 0x989680;\n\t"
        "@P bra D_%=;\n\t"
        "bra W_%=;\n\t"
        "D_%=:\n\t}"
        :: "r"(mbar), "r"(parity) : "memory");
}
__device__ __forceinline__ void fence_proxy_async_s() {
    asm volatile("fence.proxy.async.shared::cta;" ::: "memory");
}

// block-reduce one float over 256 threads -> returned valid in thread 0
__device__ __forceinline__ float block_sum(float v, float* sh8, int t) {
    #pragma unroll
    for (int o = 16; o > 0; o >>= 1) v += __shfl_down_sync(0xffffffffu, v, o);
    if ((t & 31) == 0) sh8[t >> 5] = v;
    __syncthreads();
    float r = 0.f;
    if (t < 8) {
        r = sh8[t];
        #pragma unroll
        for (int o = 4; o > 0; o >>= 1) r += __shfl_down_sync(0xffu, r, o);
    }
    __syncthreads();
    return r;
}

__global__ __launch_bounds__(NTHREADS)
void stability_loss_kernel(const float* __restrict__ x, float* __restrict__ out)
{
    __shared__ alignas(128) char stg[NSTAGE][STAGE_BYTES];   // 32 KB
    __shared__ alignas(16)   uint64_t mb[NSTAGE];
    __shared__ float4 sh_comb[128];
    __shared__ float  sh_red[8];
    __shared__ unsigned sh_old, sh_old2;

    const int t     = threadIdx.x;
    const int b     = blockIdx.x;
    const int cg    = b & (CG - 1);
    const int chunk = b >> 3;

    const uint32_t mb_addr0 = smem_u32(&mb[0]);

    // gmem base of this block's tile: rows [chunk*128, +128), cols [cg*512, +512)
    const char* gbase = (const char*)x +
        ((size_t)chunk * ROWS_PER_CHUNK * D_COLS + (size_t)cg * COLS_PER_CG) * 4;
    const size_t row_pitch = (size_t)D_COLS * 4;   // 16 KB

    // ---- init barriers + prologue fills ----
    if (t == 0) {
        #pragma unroll
        for (int s = 0; s < NSTAGE; ++s) mbar_init(mb_addr0 + 8 * s, 1);
    }
    __syncthreads();

    if (t == 0) {
        #pragma unroll
        for (int i = 0; i < NSTAGE; ++i) {
            uint32_t mba = mb_addr0 + 8 * i;
            uint32_t dst = smem_u32(&stg[i][0]);
            const char* src = gbase + (size_t)i * STAGE_ROWS * row_pitch;
            mbar_expect_tx(mba, STAGE_BYTES);
            #pragma unroll
            for (int j = 0; j < STAGE_ROWS; ++j)
                bulk_g2s(dst + j * SEG_BYTES, src + (size_t)j * row_pitch,
                         SEG_BYTES, mba);
        }
    }

    // ---- phase 1: pipelined stream + accumulate ----
    const int p = t & 127;        // float4 column position within group
    const int h = t >> 7;         // half: rows {h, h+2} of each stage

    float4 cs = make_float4(0.f, 0.f, 0.f, 0.f);
    float  ss = 0.f;

    for (int i = 0; i < NITER; ++i) {
        const int slot = i & (NSTAGE - 1);
        mbar_wait(mb_addr0 + 8 * slot, (i >> 2) & 1);

        const float4* sv = reinterpret_cast<const float4*>(&stg[slot][0]);
        float4 v0 = sv[h * 128 + p];
        float4 v1 = sv[(h + 2) * 128 + p];
        cs.x += v0.x + v1.x;  cs.y += v0.y + v1.y;
        cs.z += v0.z + v1.z;  cs.w += v0.w + v1.w;
        ss += v0.x*v0.x + v0.y*v0.y + v0.z*v0.z + v0.w*v0.w
            + v1.x*v1.x + v1.y*v1.y + v1.z*v1.z + v1.w*v1.w;

        __syncthreads();   // everyone done reading slot

        if (t == 0 && i + NSTAGE < NITER) {
            const int ni = i + NSTAGE;
            uint32_t mba = mb_addr0 + 8 * slot;
            uint32_t dst = smem_u32(&stg[slot][0]);
            const char* src = gbase + (size_t)ni * STAGE_ROWS * row_pitch;
            fence_proxy_async_s();
            mbar_expect_tx(mba, STAGE_BYTES);
            #pragma unroll
            for (int j = 0; j < STAGE_ROWS; ++j)
                bulk_g2s(dst + j * SEG_BYTES, src + (size_t)j * row_pitch,
                         SEG_BYTES, mba);
        }
    }

    // combine the two halves' column sums; threads 0..127 own the columns
    if (h == 1) sh_comb[p] = cs;
    __syncthreads();
    if (h == 0) {
        float4 o = sh_comb[p];
        cs.x += o.x; cs.y += o.y; cs.z += o.z; cs.w += o.w;
        reinterpret_cast<float4*>(g_part)[(size_t)(cg * RC + chunk) * 128 + p] = cs;
    }

    // block-reduce sumsq
    {
        float tot = block_sum(ss, sh_red, t);
        if (t == 0) g_ss_part[b] = tot;
    }

    // ---- group counter: last arrival of this column group becomes deputy ----
    __threadfence();
    if (t == 0) sh_old = atomicAdd(&g_cnt_grp[cg], 1u);
    __syncthreads();
    if (sh_old != RC - 1) return;

    if (t == 0) g_cnt_grp[cg] = 0;   // reset for next graph replay
    __threadfence();

    // ---- deputy: reduce this group's 64 chunk-partials, square, sum ----
    {
        // thread t: position p (0..127), half h sums chunks [h*32, h*32+32)
        const float4* P = reinterpret_cast<const float4*>(g_part);
        float4 s = make_float4(0.f, 0.f, 0.f, 0.f);
        const int c0 = cg * RC + h * 32;
        #pragma unroll 8
        for (int c = 0; c < 32; ++c) {
            float4 v = __ldcg(&P[(size_t)(c0 + c) * 128 + p]);
            s.x += v.x; s.y += v.y; s.z += v.z; s.w += v.w;
        }
        if (h == 1) sh_comb[p] = s;
        __syncthreads();
        float sq = 0.f;
        if (h == 0) {
            float4 o = sh_comb[p];
            s.x += o.x; s.y += o.y; s.z += o.z; s.w += o.w;
            sq = s.x*s.x + s.y*s.y + s.z*s.z + s.w*s.w;
        }
        float csq = block_sum(sq, sh_red, t);

        // group sumsq: 64 values at stride CG
        float gss = 0.f;
        if (t < RC) gss = __ldcg(&g_ss_part[cg + CG * t]);
        gss = block_sum(gss, sh_red, t);

        if (t == 0) {
            g_colsq[cg]  = csq;
            g_ss_grp[cg] = gss;
        }
    }

    // ---- final counter: last deputy folds 8+8 scalars ----
    __threadfence();
    if (t == 0) sh_old2 = atomicAdd(&g_cnt_final, 1u);
    __syncthreads();
    if (sh_old2 != CG - 1) return;

    if (t == 0) {
        g_cnt_final = 0;             // reset for next graph replay
        __threadfence();
        float ss_tot = 0.f, csq_tot = 0.f;
        #pragma unroll
        for (int i = 0; i < CG; ++i) {
            ss_tot  += __ldcg(&g_ss_grp[i]);
            csq_tot += __ldcg(&g_colsq[i]);
        }
        out[0] = (float)N_ROWS * ss_tot - csq_tot;
    }
}

extern "C" void kernel_launch(void* const* d_in, const int* in_sizes, int n_in,
                              void* d_out, int out_size)
{
    const float* x = (const float*)d_in[0];
    float* out = (float*)d_out;
    (void)in_sizes; (void)n_in; (void)out_size;

    stability_loss_kernel<<<NBLOCKS, NTHREADS>>>(x, out);
}